// round 3
// baseline (speedup 1.0000x reference)
#include <cuda_runtime.h>

// ============================================================================
// Problem constants
// ============================================================================
#define NFEAT 32
#define MAX_ATOMS 10000
#define NPATHS 19

// Scratch: per-atom B = A @ W1   (10000 * 9 * 32 floats = 11.52 MB)
__device__ float g_B[MAX_ATOMS * 9 * NFEAT];

// ============================================================================
// constexpr Clebsch-Gordan machinery — bit-faithful port of the reference
// (_cg_complex, _U, _real_cg), evaluated at COMPILE TIME so every coefficient
// becomes an FFMA immediate in SASS.
// ============================================================================
__host__ __device__ constexpr double cfact(int n) {
    double r = 1.0;
    for (int i = 2; i <= n; ++i) r *= (double)i;
    return r;
}
__host__ __device__ constexpr double csqrt_(double x) {
    if (x <= 0.0) return 0.0;
    double g = x < 1.0 ? 1.0 : x;
    for (int i = 0; i < 80; ++i) g = 0.5 * (g + x / g);
    return g;
}
__host__ __device__ constexpr int iabs_(int x) { return x < 0 ? -x : x; }

__host__ __device__ constexpr double cg_c(int j1, int m1, int j2, int m2, int j3, int m3) {
    if (m1 + m2 != m3) return 0.0;
    if (j3 < iabs_(j1 - j2) || j3 > j1 + j2) return 0.0;
    if (iabs_(m1) > j1 || iabs_(m2) > j2 || iabs_(m3) > j3) return 0.0;
    double pref = csqrt_((2.0 * j3 + 1.0) * cfact(j3 + j1 - j2) * cfact(j3 - j1 + j2) *
                         cfact(j1 + j2 - j3) / cfact(j1 + j2 + j3 + 1));
    pref *= csqrt_(cfact(j3 + m3) * cfact(j3 - m3) * cfact(j1 - m1) * cfact(j1 + m1) *
                   cfact(j2 - m2) * cfact(j2 + m2));
    double s = 0.0;
    for (int k = 0; k <= j1 + j2 - j3; ++k) {
        int d1 = j1 + j2 - j3 - k, d2 = j1 - m1 - k, d3 = j2 + m2 - k;
        int d4 = j3 - j2 + m1 + k, d5 = j3 - j1 - m2 + k;
        if (d1 < 0 || d2 < 0 || d3 < 0 || d4 < 0 || d5 < 0) continue;
        double den = cfact(k) * cfact(d1) * cfact(d2) * cfact(d3) * cfact(d4) * cfact(d5);
        s += ((k & 1) ? -1.0 : 1.0) / den;
    }
    return pref * s;
}

struct CPX { double re, im; };
__host__ __device__ constexpr CPX cmulc(CPX a, CPX b) {
    return CPX{a.re * b.re - a.im * b.im, a.re * b.im + a.im * b.re};
}
// U(l)[real_row m_r, complex_col m_c]  (reference _U convention)
__host__ __device__ constexpr CPX Uent(int l, int mr, int mc) {
    (void)l;
    double is2 = 1.0 / csqrt_(2.0);
    if (mr > 0) {
        if (mc == mr)  return CPX{((mr & 1) ? -1.0 : 1.0) * is2, 0.0};
        if (mc == -mr) return CPX{is2, 0.0};
    } else if (mr == 0) {
        if (mc == 0) return CPX{1.0, 0.0};
    } else {
        int mu = -mr;
        if (mc == mr) return CPX{0.0, is2};
        if (mc == mu) return CPX{0.0, -((mu & 1) ? -1.0 : 1.0) * is2};
    }
    return CPX{0.0, 0.0};
}

__host__ __device__ constexpr double real_cg(int l1, int l2, int l3, int a, int b, int c) {
    int m1 = a - l1, m2 = b - l2, m3 = c - l3;
    double re = 0.0, im = 0.0;
    for (int sx = 0; sx < 2; ++sx) {
        if (sx && m1 == 0) continue;
        int x = sx ? -m1 : m1;
        CPX u1 = Uent(l1, m1, x); u1.im = -u1.im;          // conj
        for (int sy = 0; sy < 2; ++sy) {
            if (sy && m2 == 0) continue;
            int y = sy ? -m2 : m2;
            CPX u2 = Uent(l2, m2, y); u2.im = -u2.im;      // conj
            for (int sz = 0; sz < 2; ++sz) {
                if (sz && m3 == 0) continue;
                int z = sz ? -m3 : m3;
                CPX u3 = Uent(l3, m3, z);                  // no conj
                double cg = cg_c(l1, x, l2, y, l3, z);
                if (cg == 0.0) continue;
                CPX t = cmulc(cmulc(u1, u2), u3);
                re += t.re * cg;
                im += t.im * cg;
            }
        }
    }
    return ((l1 + l2 + l3) & 1) ? im : re;
}

// Path table, same enumeration order as reference _build_paths()
__host__ __device__ constexpr int PL1[NPATHS] = {0,0,0,1,1,1,1,1,1,1,2,2,2,2,2,2,2,2,2};
__host__ __device__ constexpr int PL2[NPATHS] = {0,1,2,0,1,1,1,2,2,2,0,1,1,1,2,2,2,2,2};
__host__ __device__ constexpr int PL3[NPATHS] = {0,1,2,1,0,1,2,1,2,3,2,1,2,3,0,1,2,3,4};

// compile-time for
template <int I> struct IC { static constexpr int v = I; };
template <int I, int N, class F>
__device__ __forceinline__ void sfor(F&& f) {
    if constexpr (I < N) {
        f(IC<I>{});
        sfor<I + 1, N>(f);
    }
}

__device__ __forceinline__ float wsum(float v) {
    v += __shfl_xor_sync(0xffffffffu, v, 16);
    v += __shfl_xor_sync(0xffffffffu, v, 8);
    v += __shfl_xor_sync(0xffffffffu, v, 4);
    v += __shfl_xor_sync(0xffffffffu, v, 2);
    v += __shfl_xor_sync(0xffffffffu, v, 1);
    return v;
}

// ============================================================================
// Kernel 1: per-atom B = A @ W1   (tiny)
// ============================================================================
__global__ void atom_dense_kernel(const float* __restrict__ A,
                                  const float* __restrict__ W1, int n_rows) {
    __shared__ float w[1024];
    for (int x = threadIdx.x; x < 1024; x += blockDim.x) w[x] = W1[x];
    __syncthreads();
    int lim = n_rows < MAX_ATOMS * 9 ? n_rows : MAX_ATOMS * 9;
    int total = lim * 32;
    for (int idx = blockIdx.x * blockDim.x + threadIdx.x; idx < total;
         idx += gridDim.x * blockDim.x) {
        int f = idx & 31;
        int row = idx >> 5;
        const float* ar = A + row * 32;
        float acc = 0.f;
#pragma unroll
        for (int g = 0; g < 32; ++g) acc = fmaf(ar[g], w[g * 32 + f], acc);
        g_B[idx] = acc;
    }
}

// ============================================================================
// Kernel 2: fused per-edge pipeline. warp = edge, lane = feature.
// ============================================================================
__global__ void __launch_bounds__(128) edge_kernel(
    const int* __restrict__ nbr, const float* __restrict__ disp,
    const float* __restrict__ b1, const float* __restrict__ lng,
    const float* __restrict__ lnb, const float* __restrict__ W2,
    const float* __restrict__ b2, const float* __restrict__ Wb,
    const float* __restrict__ bbv, const float* __restrict__ tpw_g,
    float* __restrict__ out, int E) {
    const int lane = threadIdx.x & 31;
    const int wid = (blockIdx.x * blockDim.x + threadIdx.x) >> 5;
    const int nw = (gridDim.x * blockDim.x) >> 5;

    // per-lane parameters held in registers across the edge loop
    float w2c[32], wbc[32];
#pragma unroll
    for (int f = 0; f < 32; ++f) {
        w2c[f] = W2[f * 32 + lane];   // column 'lane' of W2
        wbc[f] = Wb[f * 32 + lane];   // column 'lane' of Wb
    }
    float tpw[NPATHS];
#pragma unroll
    for (int p = 0; p < NPATHS; ++p) tpw[p] = tpw_g[p * 32 + lane];
    const float b1v = b1[lane], b2v = b2[lane], bbc = bbv[lane], betav = lnb[lane];
    const float gm0 = lng[lane], gm1 = lng[32 + lane], gm2 = lng[64 + lane];

    for (int e = wid; e < E; e += nw) {
        const int ia = nbr[2 * e], ja = nbr[2 * e + 1];

        // ---- y0 = B[i] + B[j] (+ b1 on scalar channel) ----
        float y0[9];
#pragma unroll
        for (int m = 0; m < 9; ++m)
            y0[m] = g_B[(ia * 9 + m) * 32 + lane] + g_B[(ja * 9 + m) * 32 + lane];
        y0[0] += b1v;

        // ---- equivariant layernorm ----
        float yln[9];
        {
            float s = y0[0];
            float mu = wsum(s) * (1.f / 32.f);
            float d = s - mu;
            float var = wsum(d * d) * (1.f / 32.f);
            yln[0] = d / sqrtf(var + 1e-6f) * gm0 + betav;

            float ss1 = y0[1] * y0[1] + y0[2] * y0[2] + y0[3] * y0[3];
            float inv1 = gm1 / sqrtf(wsum(ss1) * (1.f / 96.f) + 1e-6f);
            yln[1] = y0[1] * inv1; yln[2] = y0[2] * inv1; yln[3] = y0[3] * inv1;

            float ss2 = y0[4] * y0[4] + y0[5] * y0[5] + y0[6] * y0[6] +
                        y0[7] * y0[7] + y0[8] * y0[8];
            float inv2 = gm2 / sqrtf(wsum(ss2) * (1.f / 160.f) + 1e-6f);
#pragma unroll
            for (int m = 4; m < 9; ++m) yln[m] = y0[m] * inv2;
        }

        // ---- mish gate ----
        float yg[9];
        {
            float s = yln[0];
            float sp = fmaxf(s, 0.f) + log1pf(expf(-fabsf(s)));  // stable softplus
            float th = tanhf(sp);
            float sig = 1.f / (1.f + expf(-s));
            yg[0] = s * th;
            float dg = th + s * (1.f - th * th) * sig;
#pragma unroll
            for (int m = 1; m < 9; ++m) yg[m] = yln[m] * dg;
        }

        // ---- dense2 (shfl-broadcast GEMM) + residual ----
        float y2[9];
#pragma unroll
        for (int m = 0; m < 9; ++m) y2[m] = 0.f;
#pragma unroll
        for (int f = 0; f < 32; ++f) {
#pragma unroll
            for (int m = 0; m < 9; ++m) {
                float v = __shfl_sync(0xffffffffu, yg[m], f);
                y2[m] = fmaf(v, w2c[f], y2[m]);
            }
        }
        y2[0] += b2v;
#pragma unroll
        for (int m = 0; m < 9; ++m) y2[m] += y0[m];

        // ---- bond basis: bexp[m][g] = sh[m]*radW[g] + bb δ_{m0} ----
        float dx = disp[3 * e], dy = disp[3 * e + 1], dz = disp[3 * e + 2];
        float r = sqrtf(dx * dx + dy * dy + dz * dz);
        float rinv = 1.f / fmaxf(r, 1e-12f);
        float ux = dx * rinv, uy = dy * rinv, uz = dz * rinv;
        const float s3 = 1.7320508075688772f;
        float sh[9];
        sh[0] = 1.f; sh[1] = uy; sh[2] = uz; sh[3] = ux;
        sh[4] = s3 * ux * uy; sh[5] = s3 * uy * uz;
        sh[6] = 0.5f * (3.f * uz * uz - 1.f);
        sh[7] = s3 * ux * uz; sh[8] = 0.5f * s3 * (ux * ux - uy * uy);

        float ck = (5.0f / 31.0f) * (float)lane;      // linspace(0, 5, 32)
        float dr = r - ck;
        float cut = (r < 5.f) ? 0.5f * (cosf(r * 0.6283185307179586f) + 1.f) : 0.f;
        float rad = expf(-20.48f * dr * dr) * cut;    // gamma = 0.5*(32/5)^2
        float radW = 0.f;
#pragma unroll
        for (int k = 0; k < 32; ++k)
            radW = fmaf(__shfl_sync(0xffffffffu, rad, k), wbc[k], radW);
        float av[9];
#pragma unroll
        for (int m = 0; m < 9; ++m) av[m] = sh[m] * radW;
        av[0] += bbc;

        // ---- tensor product, fully unrolled, CG coeffs as immediates ----
        float o0[25], o1[25];
#pragma unroll
        for (int c = 0; c < 25; ++c) { o0[c] = 0.f; o1[c] = 0.f; }

        sfor<0, NPATHS>([&](auto P) {
            constexpr int p = decltype(P)::v;
            constexpr int l1 = PL1[p], l2 = PL2[p], l3 = PL3[p];
            constexpr int par = (l1 + l2 + l3) & 1;
            sfor<0, 2 * l1 + 1>([&](auto Ai) {
                constexpr int aI = decltype(Ai)::v;
                float ta = av[l1 * l1 + aI] * tpw[p];
                sfor<0, 2 * l2 + 1>([&](auto Bi) {
                    constexpr int bI = decltype(Bi)::v;
                    float t = ta * y2[l2 * l2 + bI];
                    sfor<0, 2 * l3 + 1>([&](auto Ci) {
                        constexpr int cI = decltype(Ci)::v;
                        constexpr float cf = (float)real_cg(l1, l2, l3, aI, bI, cI);
                        if constexpr (cf > 1e-7f || cf < -1e-7f) {
                            if constexpr (par == 0)
                                o0[l3 * l3 + cI] = fmaf(cf, t, o0[l3 * l3 + cI]);
                            else
                                o1[l3 * l3 + cI] = fmaf(cf, t, o1[l3 * l3 + cI]);
                        }
                    });
                });
            });
        });

        // ---- store (E, 2, 25, 32) ----
        float* ob = out + (size_t)e * 1600 + lane;
#pragma unroll
        for (int c = 0; c < 25; ++c) ob[c * 32] = o0[c];
#pragma unroll
        for (int c = 0; c < 25; ++c) ob[800 + c * 32] = o1[c];
    }
}

// ============================================================================
// Launch
// ============================================================================
extern "C" void kernel_launch(void* const* d_in, const int* in_sizes, int n_in,
                              void* d_out, int out_size) {
    const float* A    = (const float*)d_in[0];
    const int*   nbr  = (const int*)d_in[1];
    const float* disp = (const float*)d_in[2];
    const float* W1   = (const float*)d_in[3];
    const float* b1   = (const float*)d_in[4];
    const float* lng  = (const float*)d_in[5];
    const float* lnb  = (const float*)d_in[6];
    const float* W2   = (const float*)d_in[7];
    const float* b2   = (const float*)d_in[8];
    const float* Wb   = (const float*)d_in[9];
    const float* bb   = (const float*)d_in[10];
    const float* tpw  = (const float*)d_in[11];
    float* out = (float*)d_out;

    int n_atoms = in_sizes[0] / (9 * NFEAT);
    int E = in_sizes[1] / 2;

    atom_dense_kernel<<<1024, 256>>>(A, W1, n_atoms * 9);
    edge_kernel<<<1184, 128>>>(nbr, disp, b1, lng, lnb, W2, b2, Wb, bb, tpw, out, E);
    (void)n_in; (void)out_size;
}

// round 7
// speedup vs baseline: 1.5382x; 1.5382x over previous
#include <cuda_runtime.h>

// ============================================================================
// Problem constants
// ============================================================================
#define NFEAT 32
#define MAX_ATOMS 10000
#define NPATHS 19

// Scratch: per-atom B = A @ W1   (10000 * 9 * 32 floats)
__device__ float g_B[MAX_ATOMS * 9 * NFEAT];

// ============================================================================
// constexpr Clebsch-Gordan machinery — bit-faithful port of the reference
// (_cg_complex, _U, _real_cg), evaluated at COMPILE TIME so every coefficient
// becomes an FFMA immediate in SASS.
// ============================================================================
__host__ __device__ constexpr double cfact(int n) {
    double r = 1.0;
    for (int i = 2; i <= n; ++i) r *= (double)i;
    return r;
}
__host__ __device__ constexpr double csqrt_(double x) {
    if (x <= 0.0) return 0.0;
    double g = x < 1.0 ? 1.0 : x;
    for (int i = 0; i < 80; ++i) g = 0.5 * (g + x / g);
    return g;
}
__host__ __device__ constexpr int iabs_(int x) { return x < 0 ? -x : x; }

__host__ __device__ constexpr double cg_c(int j1, int m1, int j2, int m2, int j3, int m3) {
    if (m1 + m2 != m3) return 0.0;
    if (j3 < iabs_(j1 - j2) || j3 > j1 + j2) return 0.0;
    if (iabs_(m1) > j1 || iabs_(m2) > j2 || iabs_(m3) > j3) return 0.0;
    double pref = csqrt_((2.0 * j3 + 1.0) * cfact(j3 + j1 - j2) * cfact(j3 - j1 + j2) *
                         cfact(j1 + j2 - j3) / cfact(j1 + j2 + j3 + 1));
    pref *= csqrt_(cfact(j3 + m3) * cfact(j3 - m3) * cfact(j1 - m1) * cfact(j1 + m1) *
                   cfact(j2 - m2) * cfact(j2 + m2));
    double s = 0.0;
    for (int k = 0; k <= j1 + j2 - j3; ++k) {
        int d1 = j1 + j2 - j3 - k, d2 = j1 - m1 - k, d3 = j2 + m2 - k;
        int d4 = j3 - j2 + m1 + k, d5 = j3 - j1 - m2 + k;
        if (d1 < 0 || d2 < 0 || d3 < 0 || d4 < 0 || d5 < 0) continue;
        double den = cfact(k) * cfact(d1) * cfact(d2) * cfact(d3) * cfact(d4) * cfact(d5);
        s += ((k & 1) ? -1.0 : 1.0) / den;
    }
    return pref * s;
}

struct CPX { double re, im; };
__host__ __device__ constexpr CPX cmulc(CPX a, CPX b) {
    return CPX{a.re * b.re - a.im * b.im, a.re * b.im + a.im * b.re};
}
__host__ __device__ constexpr CPX Uent(int l, int mr, int mc) {
    (void)l;
    double is2 = 1.0 / csqrt_(2.0);
    if (mr > 0) {
        if (mc == mr)  return CPX{((mr & 1) ? -1.0 : 1.0) * is2, 0.0};
        if (mc == -mr) return CPX{is2, 0.0};
    } else if (mr == 0) {
        if (mc == 0) return CPX{1.0, 0.0};
    } else {
        int mu = -mr;
        if (mc == mr) return CPX{0.0, is2};
        if (mc == mu) return CPX{0.0, -((mu & 1) ? -1.0 : 1.0) * is2};
    }
    return CPX{0.0, 0.0};
}

__host__ __device__ constexpr double real_cg(int l1, int l2, int l3, int a, int b, int c) {
    int m1 = a - l1, m2 = b - l2, m3 = c - l3;
    double re = 0.0, im = 0.0;
    for (int sx = 0; sx < 2; ++sx) {
        if (sx && m1 == 0) continue;
        int x = sx ? -m1 : m1;
        CPX u1 = Uent(l1, m1, x); u1.im = -u1.im;
        for (int sy = 0; sy < 2; ++sy) {
            if (sy && m2 == 0) continue;
            int y = sy ? -m2 : m2;
            CPX u2 = Uent(l2, m2, y); u2.im = -u2.im;
            for (int sz = 0; sz < 2; ++sz) {
                if (sz && m3 == 0) continue;
                int z = sz ? -m3 : m3;
                CPX u3 = Uent(l3, m3, z);
                double cg = cg_c(l1, x, l2, y, l3, z);
                if (cg == 0.0) continue;
                CPX t = cmulc(cmulc(u1, u2), u3);
                re += t.re * cg;
                im += t.im * cg;
            }
        }
    }
    return ((l1 + l2 + l3) & 1) ? im : re;
}

// Path table, same enumeration order as reference _build_paths()
__host__ __device__ constexpr int PL1[NPATHS] = {0,0,0,1,1,1,1,1,1,1,2,2,2,2,2,2,2,2,2};
__host__ __device__ constexpr int PL2[NPATHS] = {0,1,2,0,1,1,1,2,2,2,0,1,1,1,2,2,2,2,2};
__host__ __device__ constexpr int PL3[NPATHS] = {0,1,2,1,0,1,2,1,2,3,2,1,2,3,0,1,2,3,4};

template <int I> struct IC { static constexpr int v = I; };
template <int I, int N, class F>
__device__ __forceinline__ void sfor(F&& f) {
    if constexpr (I < N) {
        f(IC<I>{});
        sfor<I + 1, N>(f);
    }
}

__device__ __forceinline__ float wsum(float v) {
    v += __shfl_xor_sync(0xffffffffu, v, 16);
    v += __shfl_xor_sync(0xffffffffu, v, 8);
    v += __shfl_xor_sync(0xffffffffu, v, 4);
    v += __shfl_xor_sync(0xffffffffu, v, 2);
    v += __shfl_xor_sync(0xffffffffu, v, 1);
    return v;
}

// ============================================================================
// Kernel 1: per-atom B = A @ W1.  warp = row, W1 column resident in registers.
// ============================================================================
__global__ void __launch_bounds__(128) atom_dense_kernel(
    const float* __restrict__ A, const float* __restrict__ W1, int n_rows) {
    const int lane = threadIdx.x & 31;
    float wcol[32];
#pragma unroll
    for (int g = 0; g < 32; ++g) wcol[g] = W1[g * 32 + lane];
    const int wid = (blockIdx.x * blockDim.x + threadIdx.x) >> 5;
    const int nw = (gridDim.x * blockDim.x) >> 5;
    for (int row = wid; row < n_rows; row += nw) {
        const float4* ar = (const float4*)(A + (size_t)row * 32);
        float acc = 0.f;
#pragma unroll
        for (int q = 0; q < 8; ++q) {
            float4 v = ar[q];
            acc = fmaf(v.x, wcol[4 * q + 0], acc);
            acc = fmaf(v.y, wcol[4 * q + 1], acc);
            acc = fmaf(v.z, wcol[4 * q + 2], acc);
            acc = fmaf(v.w, wcol[4 * q + 3], acc);
        }
        g_B[(size_t)row * 32 + lane] = acc;
    }
}

// ============================================================================
// Kernel 2: fused per-edge pipeline. warp = edge, lane = feature.
// SHFL GEMMs replaced by smem-staged uniform LDS.128 broadcasts.
// ============================================================================
__global__ void __launch_bounds__(128, 4) edge_kernel(
    const int* __restrict__ nbr, const float* __restrict__ disp,
    const float* __restrict__ b1, const float* __restrict__ lng,
    const float* __restrict__ lnb, const float* __restrict__ W2,
    const float* __restrict__ b2, const float* __restrict__ Wb,
    const float* __restrict__ bbv, const float* __restrict__ tpw_g,
    float* __restrict__ out, int E) {
    __shared__ float s_wb[1024];            // Wb[k][g]
    __shared__ float s_tpw[NPATHS * 32];    // tp_w[p][g]
    __shared__ float s_yg[4][9][32];        // per-warp gated features
    __shared__ float s_rad[4][32];          // per-warp radial basis

    const int lane = threadIdx.x & 31;
    const int wib = threadIdx.x >> 5;

    for (int x = threadIdx.x; x < 1024; x += blockDim.x) s_wb[x] = Wb[x];
    for (int x = threadIdx.x; x < NPATHS * 32; x += blockDim.x) s_tpw[x] = tpw_g[x];
    __syncthreads();

    // hot parameters in registers
    float w2c[32];
#pragma unroll
    for (int f = 0; f < 32; ++f) w2c[f] = W2[f * 32 + lane];  // column 'lane' of W2
    const float b1v = b1[lane], b2v = b2[lane], bbc = bbv[lane], betav = lnb[lane];
    const float gm0 = lng[lane], gm1 = lng[32 + lane], gm2 = lng[64 + lane];

    const int wid = (blockIdx.x * blockDim.x + threadIdx.x) >> 5;
    const int nw = (gridDim.x * blockDim.x) >> 5;
    const int2* __restrict__ nbr2 = (const int2*)nbr;

    for (int e = wid; e < E; e += nw) {
        const int2 ij = nbr2[e];

        // ---- y0 = B[i] + B[j] (+ b1 on scalar channel) ----
        float y0[9];
#pragma unroll
        for (int m = 0; m < 9; ++m)
            y0[m] = g_B[((size_t)ij.x * 9 + m) * 32 + lane] +
                    g_B[((size_t)ij.y * 9 + m) * 32 + lane];
        y0[0] += b1v;

        // ---- equivariant layernorm ----
        float yg[9];
        {
            float s = y0[0];
            float mu = wsum(s) * (1.f / 32.f);
            float d = s - mu;
            float var = wsum(d * d) * (1.f / 32.f);
            yg[0] = d * rsqrtf(var + 1e-6f) * gm0 + betav;

            float ss1 = y0[1] * y0[1] + y0[2] * y0[2] + y0[3] * y0[3];
            float inv1 = gm1 * rsqrtf(wsum(ss1) * (1.f / 96.f) + 1e-6f);
            yg[1] = y0[1] * inv1; yg[2] = y0[2] * inv1; yg[3] = y0[3] * inv1;

            float ss2 = y0[4] * y0[4] + y0[5] * y0[5] + y0[6] * y0[6] +
                        y0[7] * y0[7] + y0[8] * y0[8];
            float inv2 = gm2 * rsqrtf(wsum(ss2) * (1.f / 160.f) + 1e-6f);
#pragma unroll
            for (int m = 4; m < 9; ++m) yg[m] = y0[m] * inv2;
        }

        // ---- mish gate (fast-math) ----
        {
            float s = yg[0];
            float ea = __expf(-fabsf(s));                       // e^{-|s|}
            float sp = fmaxf(s, 0.f) + __logf(1.f + ea);        // softplus
            float E2 = __expf(-2.f * sp);
            float th = __fdividef(1.f - E2, 1.f + E2);          // tanh(sp), sp>=0
            float i1 = __fdividef(1.f, 1.f + ea);
            float sig = (s >= 0.f) ? i1 : 1.f - i1;             // sigmoid(s)
            yg[0] = s * th;
            float dg = th + s * (1.f - th * th) * sig;
#pragma unroll
            for (int m = 1; m < 9; ++m) yg[m] *= dg;
        }

        // ---- bond basis radial part ----
        float dx = disp[3 * e], dy = disp[3 * e + 1], dz = disp[3 * e + 2];
        float r = sqrtf(dx * dx + dy * dy + dz * dz);
        float rinv = __fdividef(1.f, fmaxf(r, 1e-12f));
        float ux = dx * rinv, uy = dy * rinv, uz = dz * rinv;

        float ck = (5.0f / 31.0f) * (float)lane;                // linspace(0,5,32)
        float dr = r - ck;
        float cut = (r < 5.f) ? 0.5f * (__cosf(r * 0.6283185307179586f) + 1.f) : 0.f;
        float rad = __expf(-20.48f * dr * dr) * cut;            // gamma=0.5*(32/5)^2

        // ---- stage to smem (ends prior-iteration reads first) ----
        __syncwarp();
#pragma unroll
        for (int m = 0; m < 9; ++m) s_yg[wib][m][lane] = yg[m];
        s_rad[wib][lane] = rad;
        __syncwarp();

        // ---- radW = rad @ Wb  (uniform LDS.128 of rad + per-lane Wb column) ----
        float radW = 0.f;
        {
            const float4* rq = (const float4*)s_rad[wib];
#pragma unroll
            for (int q = 0; q < 8; ++q) {
                float4 rv = rq[q];
                radW = fmaf(rv.x, s_wb[(4 * q + 0) * 32 + lane], radW);
                radW = fmaf(rv.y, s_wb[(4 * q + 1) * 32 + lane], radW);
                radW = fmaf(rv.z, s_wb[(4 * q + 2) * 32 + lane], radW);
                radW = fmaf(rv.w, s_wb[(4 * q + 3) * 32 + lane], radW);
            }
        }
        const float s3 = 1.7320508075688772f;
        float av[9];
        av[0] = radW + bbc;
        av[1] = uy * radW; av[2] = uz * radW; av[3] = ux * radW;
        av[4] = s3 * ux * uy * radW;
        av[5] = s3 * uy * uz * radW;
        av[6] = 0.5f * (3.f * uz * uz - 1.f) * radW;
        av[7] = s3 * ux * uz * radW;
        av[8] = 0.5f * s3 * (ux * ux - uy * uy) * radW;

        // ---- dense2 via uniform LDS.128 broadcast + register W2 column ----
        float y2[9];
#pragma unroll
        for (int m = 0; m < 9; ++m) y2[m] = 0.f;
        {
            const float4* yq = (const float4*)&s_yg[wib][0][0];
#pragma unroll
            for (int q = 0; q < 8; ++q) {
#pragma unroll
                for (int m = 0; m < 9; ++m) {
                    float4 v = yq[m * 8 + q];
                    y2[m] = fmaf(v.x, w2c[4 * q + 0], y2[m]);
                    y2[m] = fmaf(v.y, w2c[4 * q + 1], y2[m]);
                    y2[m] = fmaf(v.z, w2c[4 * q + 2], y2[m]);
                    y2[m] = fmaf(v.w, w2c[4 * q + 3], y2[m]);
                }
            }
        }
        y2[0] += b2v;
#pragma unroll
        for (int m = 0; m < 9; ++m) y2[m] += y0[m];

        // ---- tensor product per (parity, l3) block; store immediately ----
        float* ob = out + (size_t)e * 1600 + lane;

        auto do_group = [&](auto PARc, auto L3c) {
            constexpr int PAR = decltype(PARc)::v;
            constexpr int L3 = decltype(L3c)::v;
            float acc[2 * L3 + 1];
#pragma unroll
            for (int c = 0; c < 2 * L3 + 1; ++c) acc[c] = 0.f;
            sfor<0, NPATHS>([&](auto P) {
                constexpr int p = decltype(P)::v;
                constexpr int l1 = PL1[p], l2 = PL2[p], l3 = PL3[p];
                constexpr int par = (l1 + l2 + l3) & 1;
                if constexpr (l3 == L3 && par == PAR) {
                    float tw = s_tpw[p * 32 + lane];
                    sfor<0, 2 * l1 + 1>([&](auto Ai) {
                        constexpr int aI = decltype(Ai)::v;
                        float ta = av[l1 * l1 + aI] * tw;
                        sfor<0, 2 * l2 + 1>([&](auto Bi) {
                            constexpr int bI = decltype(Bi)::v;
                            float t = ta * y2[l2 * l2 + bI];
                            sfor<0, 2 * l3 + 1>([&](auto Ci) {
                                constexpr int cI = decltype(Ci)::v;
                                constexpr float cf = (float)real_cg(l1, l2, l3, aI, bI, cI);
                                if constexpr (cf > 1e-7f || cf < -1e-7f)
                                    acc[cI] = fmaf(cf, t, acc[cI]);
                            });
                        });
                    });
                }
            });
            float* og = ob + (PAR * 25 + L3 * L3) * 32;
#pragma unroll
            for (int c = 0; c < 2 * L3 + 1; ++c) og[c * 32] = acc[c];
        };

        do_group(IC<0>{}, IC<0>{});
        do_group(IC<0>{}, IC<1>{});
        do_group(IC<0>{}, IC<2>{});
        do_group(IC<0>{}, IC<3>{});
        do_group(IC<0>{}, IC<4>{});
        do_group(IC<1>{}, IC<1>{});
        do_group(IC<1>{}, IC<2>{});
        do_group(IC<1>{}, IC<3>{});

        // structurally-zero output blocks: (par=1, l3=0) and (par=1, l3=4)
        ob[(25 + 0) * 32] = 0.f;
#pragma unroll
        for (int c = 16; c < 25; ++c) ob[(25 + c) * 32] = 0.f;
    }
}

// ============================================================================
// Launch
// ============================================================================
extern "C" void kernel_launch(void* const* d_in, const int* in_sizes, int n_in,
                              void* d_out, int out_size) {
    const float* A    = (const float*)d_in[0];
    const int*   nbr  = (const int*)d_in[1];
    const float* disp = (const float*)d_in[2];
    const float* W1   = (const float*)d_in[3];
    const float* b1   = (const float*)d_in[4];
    const float* lng  = (const float*)d_in[5];
    const float* lnb  = (const float*)d_in[6];
    const float* W2   = (const float*)d_in[7];
    const float* b2   = (const float*)d_in[8];
    const float* Wb   = (const float*)d_in[9];
    const float* bb   = (const float*)d_in[10];
    const float* tpw  = (const float*)d_in[11];
    float* out = (float*)d_out;

    int n_atoms = in_sizes[0] / (9 * NFEAT);
    int E = in_sizes[1] / 2;

    atom_dense_kernel<<<592, 128>>>(A, W1, n_atoms * 9);
    edge_kernel<<<592, 128>>>(nbr, disp, b1, lng, lnb, W2, b2, Wb, bb, tpw, out, E);
    (void)n_in; (void)out_size;
}